// round 12
// baseline (speedup 1.0000x reference)
#include <cuda_runtime.h>
#include <cuda_bf16.h>

// Haar DWT (pywt 'haar', torch-style flipped filters + cross-correlation):
//   a=x[h,w] b=x[h,w+1] c=x[h+1,w] d=x[h+1,w+1]  (zero pad right/bottom)
//   LL=.5(a+b+c+d)  LH=.5(a+b-c-d)  HL=.5(a-b+c-d)  HH=.5(a-b-c+d)
// out[b, 4c+k, h, w]  ->  plane index 4*(b*C+c)+k
//
// R12: hybrid of the two best measured coordinates: R3's warp-per-row
// MLP=4 shape (4x front-batched LDG.128 + 8x STG.128 per thread, all
// 512B/warp, shuffle neighbors) at R10's 128-thread CTA size.
// Block (32,4) = 4 warps x 1 row; grid (H/4, B*C) = 32768 CTAs.

#define DWT_W 256
#define DWT_H 256
#define W4    (DWT_W / 4)
#define PLANE4 ((size_t)DWT_H * W4)
#define FULL  0xffffffffu

__device__ __forceinline__ void subbands_store(
    float4* __restrict__ ob, size_t oidx,
    float4 T, float4 B, float tn, float bn)
{
    const float ts0 = T.x + T.y, ts1 = T.y + T.z, ts2 = T.z + T.w, ts3 = T.w + tn;
    const float td0 = T.x - T.y, td1 = T.y - T.z, td2 = T.z - T.w, td3 = T.w - tn;
    const float bs0 = B.x + B.y, bs1 = B.y + B.z, bs2 = B.z + B.w, bs3 = B.w + bn;
    const float bd0 = B.x - B.y, bd1 = B.y - B.z, bd2 = B.z - B.w, bd3 = B.w - bn;

    float4 v;
    v.x = 0.5f * (ts0 + bs0); v.y = 0.5f * (ts1 + bs1);
    v.z = 0.5f * (ts2 + bs2); v.w = 0.5f * (ts3 + bs3);
    __stcs(ob + oidx, v);                                   // LL

    v.x = 0.5f * (ts0 - bs0); v.y = 0.5f * (ts1 - bs1);
    v.z = 0.5f * (ts2 - bs2); v.w = 0.5f * (ts3 - bs3);
    __stcs(ob + PLANE4 + oidx, v);                          // LH

    v.x = 0.5f * (td0 + bd0); v.y = 0.5f * (td1 + bd1);
    v.z = 0.5f * (td2 + bd2); v.w = 0.5f * (td3 + bd3);
    __stcs(ob + 2 * PLANE4 + oidx, v);                      // HL

    v.x = 0.5f * (td0 - bd0); v.y = 0.5f * (td1 - bd1);
    v.z = 0.5f * (td2 - bd2); v.w = 0.5f * (td3 - bd3);
    __stcs(ob + 3 * PLANE4 + oidx, v);                      // HH
}

// block (32, 4): one warp per row, 4 rows per block. grid: (H/4, B*C)
__global__ __launch_bounds__(128, 8)
void haar_dwt_kernel(const float* __restrict__ x, float* __restrict__ out)
{
    const int lane = threadIdx.x;                 // 0..31
    const int h    = blockIdx.x * 4 + threadIdx.y;
    const int bc   = blockIdx.y;

    const float4* xp4 = (const float4*)(x + (size_t)bc * DWT_H * DWT_W);
    const float4* rt  = xp4 + h * W4;

    // ---- front-batched loads: 4 independent 512B/warp LDG.128 (MLP=4) ----
    float4 t1 = rt[lane];            // row h,   cols [0,128)
    float4 t2 = rt[lane + 32];       // row h,   cols [128,256)
    float4 u1, u2;
    if (h < DWT_H - 1) {
        const float4* ru = rt + W4;
        u1 = ru[lane];               // row h+1, cols [0,128)
        u2 = ru[lane + 32];          // row h+1, cols [128,256)
    } else {
        u1 = make_float4(0.f, 0.f, 0.f, 0.f);
        u2 = u1;
    }

    // ---- horizontal neighbors via shuffle (no extra LDGs) ----
    float nt1 = __shfl_down_sync(FULL, t1.x, 1);
    float nu1 = __shfl_down_sync(FULL, u1.x, 1);
    float nt2 = __shfl_down_sync(FULL, t2.x, 1);
    float nu2 = __shfl_down_sync(FULL, u2.x, 1);
    const float t2x0 = __shfl_sync(FULL, t2.x, 0);   // col 128
    const float u2x0 = __shfl_sync(FULL, u2.x, 0);
    if (lane == 31) {
        nt1 = t2x0;            // group 1 lane 31 -> col 128
        nu1 = u2x0;
        nt2 = 0.f;             // col 256 -> zero pad
        nu2 = 0.f;
    }

    float4* ob = (float4*)out + (size_t)(4 * bc) * PLANE4;
    const size_t o1 = (size_t)h * W4 + lane;

    subbands_store(ob, o1,      t1, u1, nt1, nu1);   // cols [0,128)
    subbands_store(ob, o1 + 32, t2, u2, nt2, nu2);   // cols [128,256)
}

extern "C" void kernel_launch(void* const* d_in, const int* in_sizes, int n_in,
                              void* d_out, int out_size)
{
    const float* x = (const float*)d_in[0];
    float* out = (float*)d_out;

    const int n_planes = in_sizes[0] / (DWT_H * DWT_W);   // B*C = 512

    dim3 block(32, 4, 1);
    dim3 grid(DWT_H / 4, n_planes, 1);
    haar_dwt_kernel<<<grid, block>>>(x, out);
}

// round 13
// speedup vs baseline: 1.0234x; 1.0234x over previous
#include <cuda_runtime.h>
#include <cuda_bf16.h>

// Haar DWT (pywt 'haar', torch-style flipped filters + cross-correlation):
//   a=x[h,w] b=x[h,w+1] c=x[h+1,w] d=x[h+1,w+1]  (zero pad right/bottom)
//   LL=.5(a+b+c+d)  LH=.5(a+b-c-d)  HL=.5(a-b+c-d)  HH=.5(a-b-c+d)
// out[b, 4c+k, h, w]  ->  plane index 4*(b*C+c)+k
//
// FINAL (== R10, session best): warp = row x half-row, shuffle-based
// horizontal neighbors, 2x front-batched LDG.128 + 4x STG.128 per thread,
// every access a perfect 512B/warp transaction, streaming stores keep L2
// for input-row reuse. 128-thread CTAs (65536 blocks) for fine scheduling
// grain. 27 regs, occ ~84%, DRAM ~80% — at the HBM roofline for this
// 1:4 read:write mix (measured traffic 611 MB ~= the L2-assisted floor).

#define DWT_W 256
#define DWT_H 256
#define W4    (DWT_W / 4)
#define PLANE4 ((size_t)DWT_H * W4)
#define FULL  0xffffffffu

// block (32, 4): 4 warps = 2 rows x 2 column groups. grid: (H/2, B*C)
__global__ __launch_bounds__(128)
void haar_dwt_kernel(const float* __restrict__ x, float* __restrict__ out)
{
    const int lane = threadIdx.x;                 // 0..31
    const int g    = threadIdx.y & 1;             // column group: 0 -> [0,128), 1 -> [128,256)
    const int h    = blockIdx.x * 2 + (threadIdx.y >> 1);   // output row
    const int bc   = blockIdx.y;                  // b*C + c

    const float*  xp  = x + (size_t)bc * DWT_H * DWT_W;
    const float4* xp4 = (const float4*)xp;

    const int  col4    = 32 * g + lane;           // float4 column 0..63
    const bool has_bot = (h < DWT_H - 1);

    // ---- front-batched loads: 2 independent 512B/warp LDG.128 ----
    float4 top = xp4[h * W4 + col4];
    float4 bot = has_bot ? xp4[(h + 1) * W4 + col4]
                         : make_float4(0.f, 0.f, 0.f, 0.f);

    // ---- horizontal neighbors via shuffle; seam handled by lane 31 ----
    float tn = __shfl_down_sync(FULL, top.x, 1);
    float bn = __shfl_down_sync(FULL, bot.x, 1);
    if (lane == 31) {
        if (g == 0) {           // neighbor is col 128 (first elem of group 1)
            tn = __ldg(&xp[h * DWT_W + 128]);
            bn = has_bot ? __ldg(&xp[(h + 1) * DWT_W + 128]) : 0.0f;
        } else {                // neighbor is col 256 -> zero pad
            tn = 0.0f;
            bn = 0.0f;
        }
    }

    // ---- horizontal sums/diffs shared by the 4 subbands ----
    const float ts0 = top.x + top.y, ts1 = top.y + top.z, ts2 = top.z + top.w, ts3 = top.w + tn;
    const float td0 = top.x - top.y, td1 = top.y - top.z, td2 = top.z - top.w, td3 = top.w - tn;
    const float bs0 = bot.x + bot.y, bs1 = bot.y + bot.z, bs2 = bot.z + bot.w, bs3 = bot.w + bn;
    const float bd0 = bot.x - bot.y, bd1 = bot.y - bot.z, bd2 = bot.z - bot.w, bd3 = bot.w - bn;

    float4* ob = (float4*)out + (size_t)(4 * bc) * PLANE4;
    const size_t oidx = (size_t)h * W4 + col4;

    float4 v;
    v.x = 0.5f * (ts0 + bs0); v.y = 0.5f * (ts1 + bs1);
    v.z = 0.5f * (ts2 + bs2); v.w = 0.5f * (ts3 + bs3);
    __stcs(ob + oidx, v);                                   // LL

    v.x = 0.5f * (ts0 - bs0); v.y = 0.5f * (ts1 - bs1);
    v.z = 0.5f * (ts2 - bs2); v.w = 0.5f * (ts3 - bs3);
    __stcs(ob + PLANE4 + oidx, v);                          // LH

    v.x = 0.5f * (td0 + bd0); v.y = 0.5f * (td1 + bd1);
    v.z = 0.5f * (td2 + bd2); v.w = 0.5f * (td3 + bd3);
    __stcs(ob + 2 * PLANE4 + oidx, v);                      // HL

    v.x = 0.5f * (td0 - bd0); v.y = 0.5f * (td1 - bd1);
    v.z = 0.5f * (td2 - bd2); v.w = 0.5f * (td3 - bd3);
    __stcs(ob + 3 * PLANE4 + oidx, v);                      // HH
}

extern "C" void kernel_launch(void* const* d_in, const int* in_sizes, int n_in,
                              void* d_out, int out_size)
{
    const float* x = (const float*)d_in[0];
    float* out = (float*)d_out;

    const int n_planes = in_sizes[0] / (DWT_H * DWT_W);   // B*C = 512

    dim3 block(32, 4, 1);
    dim3 grid(DWT_H / 2, n_planes, 1);
    haar_dwt_kernel<<<grid, block>>>(x, out);
}

// round 16
// speedup vs baseline: 1.0273x; 1.0038x over previous
#include <cuda_runtime.h>
#include <cuda_bf16.h>

// Haar DWT (pywt 'haar', torch-style flipped filters + cross-correlation):
//   a=x[h,w] b=x[h,w+1] c=x[h+1,w] d=x[h+1,w+1]  (zero pad right/bottom)
//   LL=.5(a+b+c+d)  LH=.5(a+b-c-d)  HL=.5(a-b+c-d)  HH=.5(a-b-c+d)
// out[b, 4c+k, h, w]  ->  plane index 4*(b*C+c)+k
//
// R16: 256-bit form of the L2-retention experiment. sm_103a ptxas requires
// .v8.b32 with L2::evict_last -> restructure to LDG.256/STG.256:
// warp = full row, lane owns 8 cols. 2x v8 evict_last loads (1024B/warp),
// 4x v8 .cs stores (1024B/warp), neighbor via single shuffle, no seam LDG.

#define DWT_W 256
#define DWT_H 256
#define PLANE ((size_t)DWT_H * DWT_W)
#define FULL  0xffffffffu

__device__ __forceinline__ void ld_el8(const float* p, float* v)
{
    asm("ld.global.nc.L2::evict_last.v8.b32 {%0,%1,%2,%3,%4,%5,%6,%7}, [%8];"
        : "=f"(v[0]), "=f"(v[1]), "=f"(v[2]), "=f"(v[3]),
          "=f"(v[4]), "=f"(v[5]), "=f"(v[6]), "=f"(v[7])
        : "l"(p));
}

__device__ __forceinline__ void st_cs8(float* p, const float* v)
{
    asm volatile("st.global.cs.v8.b32 [%0], {%1,%2,%3,%4,%5,%6,%7,%8};"
                 :: "l"(p),
                    "f"(v[0]), "f"(v[1]), "f"(v[2]), "f"(v[3]),
                    "f"(v[4]), "f"(v[5]), "f"(v[6]), "f"(v[7])
                 : "memory");
}

// block (32, 4): 4 warps = 4 rows. grid: (H/4, B*C)
__global__ __launch_bounds__(128)
void haar_dwt_kernel(const float* __restrict__ x, float* __restrict__ out)
{
    const int lane = threadIdx.x;                    // 0..31, owns cols [8l, 8l+8)
    const int h    = blockIdx.x * 4 + threadIdx.y;   // output row
    const int bc   = blockIdx.y;                     // b*C + c

    const float* xp = x + (size_t)bc * PLANE;
    const float* pt = xp + h * DWT_W + lane * 8;

    float t[9], b[9];
    ld_el8(pt, t);                                   // top row (always in range)
    if (h < DWT_H - 1) {
        ld_el8(pt + DWT_W, b);                       // bottom row
    } else {
#pragma unroll
        for (int i = 0; i < 8; i++) b[i] = 0.0f;
    }

    // horizontal neighbor: col 8*lane+8 = lane+1's first element
    t[8] = __shfl_down_sync(FULL, t[0], 1);
    b[8] = __shfl_down_sync(FULL, b[0], 1);
    if (lane == 31) { t[8] = 0.0f; b[8] = 0.0f; }    // col 256 -> zero pad

    float* ob = out + (size_t)(4 * bc) * PLANE + (size_t)h * DWT_W + lane * 8;

    float v[8];

    // LL = .5((t_i + t_{i+1}) + (b_i + b_{i+1}))
#pragma unroll
    for (int i = 0; i < 8; i++) v[i] = 0.5f * ((t[i] + t[i + 1]) + (b[i] + b[i + 1]));
    st_cs8(ob, v);

    // LH = .5((t_i + t_{i+1}) - (b_i + b_{i+1}))
#pragma unroll
    for (int i = 0; i < 8; i++) v[i] = 0.5f * ((t[i] + t[i + 1]) - (b[i] + b[i + 1]));
    st_cs8(ob + PLANE, v);

    // HL = .5((t_i - t_{i+1}) + (b_i - b_{i+1}))
#pragma unroll
    for (int i = 0; i < 8; i++) v[i] = 0.5f * ((t[i] - t[i + 1]) + (b[i] - b[i + 1]));
    st_cs8(ob + 2 * PLANE, v);

    // HH = .5((t_i - t_{i+1}) - (b_i - b_{i+1}))
#pragma unroll
    for (int i = 0; i < 8; i++) v[i] = 0.5f * ((t[i] - t[i + 1]) - (b[i] - b[i + 1]));
    st_cs8(ob + 3 * PLANE, v);
}

extern "C" void kernel_launch(void* const* d_in, const int* in_sizes, int n_in,
                              void* d_out, int out_size)
{
    const float* x = (const float*)d_in[0];
    float* out = (float*)d_out;

    const int n_planes = in_sizes[0] / (DWT_H * DWT_W);   // B*C = 512

    dim3 block(32, 4, 1);
    dim3 grid(DWT_H / 4, n_planes, 1);
    haar_dwt_kernel<<<grid, block>>>(x, out);
}